// round 5
// baseline (speedup 1.0000x reference)
#include <cuda_runtime.h>
#include <cuda_fp16.h>

// Problem constants (fixed by the reference: m = n = 8192, 50 Sinkhorn iters, beta=0.3)
#define MDIM  8192
#define NBLK  152          // GB300 has 152 SMs -> one full wave
#define TPB   256
#define NITER 50
#define BETA  0.3f

// ---- scratch (device globals: no allocation allowed in kernel_launch) ----
static __device__ __half g_sh[(size_t)MDIM * MDIM];     // fp16 copy of scores (128 MB)
static __device__ float  g_v[MDIM];                     // Sinkhorn v
static __device__ float  g_u[MDIM];                     // Sinkhorn u (last iteration's)
static __device__ float  g_part[(size_t)NBLK * MDIM];   // per-block column partial sums
static __device__ float  g_losspart[NBLK];              // per-block loss partials

__device__ __forceinline__ float warp_sum(float v) {
#pragma unroll
    for (int o = 16; o; o >>= 1) v += __shfl_xor_sync(0xffffffffu, v, o);
    return v;
}
__device__ __forceinline__ float warp_max(float v) {
#pragma unroll
    for (int o = 16; o; o >>= 1) v = fmaxf(v, __shfl_xor_sync(0xffffffffu, v, o));
    return v;
}

// v <- 0
__global__ void k_init_v() {
    int j = blockIdx.x * blockDim.x + threadIdx.x;
    if (j < MDIM) g_v[j] = 0.f;
}

// fp32 -> fp16 copy (one pass; iterations then read half the bytes)
__global__ void k_convert(const float* __restrict__ in) {
    size_t i = (size_t)blockIdx.x * blockDim.x + threadIdx.x;   // float4 index
    float4 f = reinterpret_cast<const float4*>(in)[i];
    union { uint2 u; __half2 h[2]; } P;
    P.h[0] = __floats2half2_rn(f.x, f.y);
    P.h[1] = __floats2half2_rn(f.z, f.w);
    reinterpret_cast<uint2*>(g_sh)[i] = P.u;
}

// One fused Sinkhorn iteration body: for each row, u_i = log_mu - LSE_j(s_ij + v_j),
// and accumulate column partials  P[b][j] = sum_{i in block} exp(s_ij + u_i).
// Thread t owns columns {g*2048 + 8t .. +7 : g=0..3}; column accumulators live in registers.
__global__ void __launch_bounds__(TPB, 1) k_iter() {
    const int tid = threadIdx.x;
    const int b   = blockIdx.x;
    const int r0  = (b * MDIM) / NBLK;
    const int r1  = ((b + 1) * MDIM) / NBLK;
    const float L2E    = 1.4426950408889634f;
    const float LOG_MU = -9.704060527839234f;   // log(1/(m+n)) = -log(16384)
    const float MUc    = 6.103515625e-5f;       // 1/16384

    float vl2e[4][8];   // v_j * log2(e) for my 32 columns (constant over rows)
    float cacc[4][8];   // column accumulators: sum_i exp(s+u+v_j)  (exp(-v_j) applied at writeout)
#pragma unroll
    for (int g = 0; g < 4; g++) {
        int cb = (g << 11) + (tid << 3);
        float4 a = *reinterpret_cast<const float4*>(g_v + cb);
        float4 c = *reinterpret_cast<const float4*>(g_v + cb + 4);
        vl2e[g][0] = a.x * L2E; vl2e[g][1] = a.y * L2E;
        vl2e[g][2] = a.z * L2E; vl2e[g][3] = a.w * L2E;
        vl2e[g][4] = c.x * L2E; vl2e[g][5] = c.y * L2E;
        vl2e[g][6] = c.z * L2E; vl2e[g][7] = c.w * L2E;
#pragma unroll
        for (int k = 0; k < 8; k++) cacc[g][k] = 0.f;
    }

    __shared__ float sred[8];

    // software pipeline: prefetch next row's 4x LDG.128 while processing current
    uint4 raw[4];
    {
        const uint4* row = reinterpret_cast<const uint4*>(g_sh + (size_t)r0 * MDIM);
#pragma unroll
        for (int g = 0; g < 4; g++) raw[g] = row[(g << 8) + tid];
    }

    for (int r = r0; r < r1; r++) {
        uint4 cur[4];
#pragma unroll
        for (int g = 0; g < 4; g++) cur[g] = raw[g];
        if (r + 1 < r1) {
            const uint4* row = reinterpret_cast<const uint4*>(g_sh + (size_t)(r + 1) * MDIM);
#pragma unroll
            for (int g = 0; g < 4; g++) raw[g] = row[(g << 8) + tid];
        }

        // e_k = exp(s + v_k)   (no max-shift needed: |s+v| < ~10 in this gauge, fp32-safe)
        float e[4][8];
        float lsum = 0.f;
#pragma unroll
        for (int g = 0; g < 4; g++) {
            union { uint4 u; __half2 h[4]; } P; P.u = cur[g];
#pragma unroll
            for (int p = 0; p < 4; p++) {
                float2 f = __half22float2(P.h[p]);
                float e0 = exp2f(fmaf(f.x, L2E, vl2e[g][2 * p]));
                float e1 = exp2f(fmaf(f.y, L2E, vl2e[g][2 * p + 1]));
                e[g][2 * p]     = e0;
                e[g][2 * p + 1] = e1;
                lsum += e0 + e1;
            }
        }

        float ws = warp_sum(lsum);
        __syncthreads();                       // guard smem reuse from previous row
        if ((tid & 31) == 0) sred[tid >> 5] = ws;
        __syncthreads();
        float S = 0.f;
#pragma unroll
        for (int w = 0; w < 8; w++) S += sred[w];   // every thread: same order, deterministic

        if (tid == 0) g_u[r] = LOG_MU - __logf(S);  // u_i (only last iteration's survives)

        // exp(s+u) = e_k * exp(M+u-... ) simplifies to e_k * (mu/S) * exp(-v_k);
        // the exp(-v_k) factor is per-column-constant -> applied once at writeout.
        float rs = MUc / S;
#pragma unroll
        for (int g = 0; g < 4; g++)
#pragma unroll
            for (int k = 0; k < 8; k++)
                cacc[g][k] = fmaf(e[g][k], rs, cacc[g][k]);
    }

    float* outp = g_part + (size_t)b * MDIM;
#pragma unroll
    for (int g = 0; g < 4; g++) {
        int cb = (g << 11) + (tid << 3);
        float4 o0, o1;
        o0.x = cacc[g][0] * exp2f(-vl2e[g][0]);
        o0.y = cacc[g][1] * exp2f(-vl2e[g][1]);
        o0.z = cacc[g][2] * exp2f(-vl2e[g][2]);
        o0.w = cacc[g][3] * exp2f(-vl2e[g][3]);
        o1.x = cacc[g][4] * exp2f(-vl2e[g][4]);
        o1.y = cacc[g][5] * exp2f(-vl2e[g][5]);
        o1.z = cacc[g][6] * exp2f(-vl2e[g][6]);
        o1.w = cacc[g][7] * exp2f(-vl2e[g][7]);
        *reinterpret_cast<float4*>(outp + cb)     = o0;
        *reinterpret_cast<float4*>(outp + cb + 4) = o1;
    }
}

// v_j = log_nu - log( sum_b P[b][j] )
__global__ void k_colreduce() {
    const float LOG_MU = -9.704060527839234f;   // log_nu == log_mu
    int j = blockIdx.x * blockDim.x + threadIdx.x;
    float s = 0.f;
#pragma unroll 8
    for (int b = 0; b < NBLK; b++) s += g_part[(size_t)b * MDIM + j];
    g_v[j] = LOG_MU - __logf(s);
}

// Final loss pass over the fp32 matrix:
//  lp = scale*s - L_i,  L_i = LSE_j(scale*s)  (max-shifted; scale=100 demands fp32 input)
//  Q_ij = exp(s+u+v+log(m+n)) = base_ij * rowq,  base = exp(s+v), rowq = exp(u - log_mu)
//  per_row = beta*(L*SumQ - scale*Sum(s*Q)) + (1-beta)*(L - scale*s_ii)
__global__ void __launch_bounds__(TPB, 1) k_final(const float* __restrict__ Sm,
                                                  const float* __restrict__ scale_p) {
    const int tid = threadIdx.x;
    const int b   = blockIdx.x;
    const int r0  = (b * MDIM) / NBLK;
    const int r1  = ((b + 1) * MDIM) / NBLK;
    const float L2E    = 1.4426950408889634f;
    const float LOG_MU = -9.704060527839234f;
    const float scale  = *scale_p;
    const float sL2E   = scale * L2E;

    float vl2e[4][8];
#pragma unroll
    for (int g = 0; g < 4; g++) {
        int cb = (g << 11) + (tid << 3);
        float4 a = *reinterpret_cast<const float4*>(g_v + cb);
        float4 c = *reinterpret_cast<const float4*>(g_v + cb + 4);
        vl2e[g][0] = a.x * L2E; vl2e[g][1] = a.y * L2E;
        vl2e[g][2] = a.z * L2E; vl2e[g][3] = a.w * L2E;
        vl2e[g][4] = c.x * L2E; vl2e[g][5] = c.y * L2E;
        vl2e[g][6] = c.z * L2E; vl2e[g][7] = c.w * L2E;
    }

    __shared__ float smax[8], sA[8], sB[8], sC[8];
    __shared__ float sdiag;
    float rowloss = 0.f;

    for (int r = r0; r < r1; r++) {
        float val[4][8];
        const float4* row = reinterpret_cast<const float4*>(Sm + (size_t)r * MDIM);
#pragma unroll
        for (int g = 0; g < 4; g++) {
            float4 a = row[(g << 9) + (tid << 1)];
            float4 c = row[(g << 9) + (tid << 1) + 1];
            val[g][0] = a.x; val[g][1] = a.y; val[g][2] = a.z; val[g][3] = a.w;
            val[g][4] = c.x; val[g][5] = c.y; val[g][6] = c.z; val[g][7] = c.w;
        }

        float m = val[0][0];
#pragma unroll
        for (int g = 0; g < 4; g++)
#pragma unroll
            for (int k = 0; k < 8; k++) m = fmaxf(m, val[g][k]);
        m = warp_max(m);

        __syncthreads();                                   // guard smem reuse
        if (tid == ((r >> 3) & 255)) sdiag = val[r >> 11][r & 7];   // owner of column r
        if ((tid & 31) == 0) smax[tid >> 5] = m;
        __syncthreads();
        float M = smax[0];
#pragma unroll
        for (int w = 1; w < 8; w++) M = fmaxf(M, smax[w]);

        float negML = -M * sL2E;
        float aE = 0.f, aB = 0.f, aSB = 0.f;
#pragma unroll
        for (int g = 0; g < 4; g++)
#pragma unroll
            for (int k = 0; k < 8; k++) {
                float s = val[g][k];
                aE += exp2f(fmaf(s, sL2E, negML));                 // exp(scale*(s-M))
                float base = exp2f(fmaf(s, L2E, vl2e[g][k]));      // exp(s+v)
                aB += base;
                aSB = fmaf(s, base, aSB);
            }
        aE = warp_sum(aE); aB = warp_sum(aB); aSB = warp_sum(aSB);
        if ((tid & 31) == 0) { int w = tid >> 5; sA[w] = aE; sB[w] = aB; sC[w] = aSB; }
        __syncthreads();

        if (tid == 0) {
            float SE = 0.f, SBv = 0.f, SSv = 0.f;
#pragma unroll
            for (int w = 0; w < 8; w++) { SE += sA[w]; SBv += sB[w]; SSv += sC[w]; }
            float L    = fmaf(scale, M, __logf(SE));
            float rowq = exp2f((g_u[r] - LOG_MU) * L2E);   // exp(u + log(m+n))
            rowloss += BETA * (L * (SBv * rowq) - scale * (SSv * rowq))
                     + (1.f - BETA) * (L - scale * sdiag);
        }
    }
    if (tid == 0) g_losspart[b] = rowloss;
}

// final scalar: mean over rows (fixed-order reduction -> deterministic)
__global__ void k_loss(float* __restrict__ out) {
    int tid = threadIdx.x;
    float v = (tid < NBLK) ? g_losspart[tid] : 0.f;
    v = warp_sum(v);
    __shared__ float sred[8];
    if ((tid & 31) == 0) sred[tid >> 5] = v;
    __syncthreads();
    if (tid == 0) {
        float t = 0.f;
#pragma unroll
        for (int w = 0; w < 8; w++) t += sred[w];
        out[0] = t / (float)MDIM;
    }
}

extern "C" void kernel_launch(void* const* d_in, const int* in_sizes, int n_in,
                              void* d_out, int out_size) {
    (void)in_sizes; (void)n_in; (void)out_size;
    const float* Sm    = (const float*)d_in[0];   // similarity_matrix [8192,8192] f32
    const float* scale = (const float*)d_in[1];   // logit_scale scalar f32
    float* out = (float*)d_out;

    k_init_v<<<MDIM / TPB, TPB>>>();
    k_convert<<<(int)(((size_t)MDIM * MDIM / 4) / TPB), TPB>>>(Sm);

    for (int it = 0; it < NITER; it++) {
        k_iter<<<NBLK, TPB>>>();
        k_colreduce<<<MDIM / TPB, TPB>>>();
    }

    k_final<<<NBLK, TPB>>>(Sm, scale);
    k_loss<<<1, TPB>>>(out);
}